// round 9
// baseline (speedup 1.0000x reference)
#include <cuda_runtime.h>

// x: (4, 32, 512, 512) fp32 ; bias: (1, 32, 1, 1) fp32
// out: [G1 | G2 | G3], each (4, 32, 512, 512) fp32
//
// G1[h,w] = (h>=1 && w>=1) ? exp(-(x[h-1,w-1]-x[h,w])^2) + bias : bias
// G2[h,w] = (w>=1)          ? exp(-(x[h,  w-1]-x[h,w])^2) + bias : bias
// G3[h,w] = (h<H-1 && w>=1) ? exp(-(x[h+1,w-1]-x[h,w])^2) + bias : bias
//
// One float4 per thread, branchless. x loads carry an L2::evict_last
// cache hint (createpolicy + ld.global.nc.L2::cache_hint) so the input
// stays L2-resident against the 403MB write stream; outputs write-through.

#define H   512
#define WV  128           // float4 per row
#define N4  8388608u      // float4 per gate tensor (4*32*512*512/4)

__device__ __forceinline__ unsigned long long mk_evict_last_policy() {
    unsigned long long pol;
    asm("createpolicy.fractional.L2::evict_last.b64 %0, 1.0;" : "=l"(pol));
    return pol;
}
__device__ __forceinline__ float4 ldg_el_v4(const float4* p, unsigned long long pol) {
    float4 r;
    asm volatile("ld.global.nc.L2::cache_hint.v4.f32 {%0,%1,%2,%3}, [%4], %5;"
                 : "=f"(r.x), "=f"(r.y), "=f"(r.z), "=f"(r.w)
                 : "l"(p), "l"(pol));
    return r;
}
__device__ __forceinline__ float ldg_el_f(const float* p, unsigned long long pol) {
    float r;
    asm volatile("ld.global.nc.L2::cache_hint.f32 %0, [%1], %2;"
                 : "=f"(r) : "l"(p), "l"(pol));
    return r;
}

__global__ __launch_bounds__(256) void embeded_gate_kernel(
    const float* __restrict__ x,
    const float* __restrict__ bias,
    float* __restrict__ out)
{
    const unsigned idx = blockIdx.x * 256u + threadIdx.x;   // == float4 linear index
    const unsigned v = idx & (WV - 1);
    const unsigned h = (idx >> 7) & (H - 1);
    const unsigned c = (idx >> 16) & 31u;

    const float bi = __ldg(&bias[c]);
    const unsigned long long pol = mk_evict_last_policy();

    const bool hup = (h > 0);
    const bool hdn = (h < H - 1);
    const bool vs  = (v > 0);

    // clamped neighbor-row float4 indices (always in-bounds)
    const unsigned iu = hup ? idx - WV : idx;
    const unsigned id = hdn ? idx + WV : idx;
    const unsigned dv = vs ? 1u : 0u;   // scalar left-neighbor offset

    const float4* __restrict__ x4 = reinterpret_cast<const float4*>(x);

    // ---- 6 unconditional, independent loads (front-batched, evict_last) ----
    const float4 cur4 = ldg_el_v4(&x4[idx], pol);
    const float4 u4   = ldg_el_v4(&x4[iu],  pol);
    const float4 d4   = ldg_el_v4(&x4[id],  pol);
    const float  lc   = ldg_el_f(&x[(idx << 2) - dv], pol);
    const float  lu   = ldg_el_f(&x[(iu  << 2) - dv], pol);
    const float  ld   = ldg_el_f(&x[(id  << 2) - dv], pol);

    const float cur[4] = {cur4.x, cur4.y, cur4.z, cur4.w};
    const float lf[4]  = {lc, cur4.x, cur4.y, cur4.z};
    const float up[4]  = {lu, u4.x,   u4.y,   u4.z};
    const float dn[4]  = {ld, d4.x,   d4.y,   d4.z};

    float g1[4], g2[4], g3[4];
#pragma unroll
    for (int k = 0; k < 4; ++k) {
        const bool wok = vs || (k > 0);     // global w index > 0
        float e1 = up[k] - cur[k];
        float e2 = lf[k] - cur[k];
        float e3 = dn[k] - cur[k];
        float v1 = __expf(-e1 * e1) + bi;
        float v2 = __expf(-e2 * e2) + bi;
        float v3 = __expf(-e3 * e3) + bi;
        g1[k] = (hup && wok) ? v1 : bi;
        g2[k] = (wok)        ? v2 : bi;
        g3[k] = (hdn && wok) ? v3 : bi;
    }

    float4* __restrict__ o4 = reinterpret_cast<float4*>(out);
    __stwt(&o4[idx],           make_float4(g1[0], g1[1], g1[2], g1[3]));
    __stwt(&o4[idx + N4],      make_float4(g2[0], g2[1], g2[2], g2[3]));
    __stwt(&o4[idx + 2u * N4], make_float4(g3[0], g3[1], g3[2], g3[3]));
}

extern "C" void kernel_launch(void* const* d_in, const int* in_sizes, int n_in,
                              void* d_out, int out_size) {
    const float* x    = (const float*)d_in[0];
    const float* bias = (const float*)d_in[1];
    float* out = (float*)d_out;

    const long long total_vec = (long long)in_sizes[0] / 4;   // 8,388,608 threads
    const int threads = 256;
    const int blocks = (int)((total_vec + threads - 1) / threads);

    embeded_gate_kernel<<<blocks, threads>>>(x, bias, out);
}

// round 10
// speedup vs baseline: 1.0124x; 1.0124x over previous
#include <cuda_runtime.h>

// x: (4, 32, 512, 512) fp32 ; bias: (1, 32, 1, 1) fp32
// out: [G1 | G2 | G3], each (4, 32, 512, 512) fp32
//
// G1[h,w] = (h>=1 && w>=1) ? exp(-(x[h-1,w-1]-x[h,w])^2) + bias : bias
// G2[h,w] = (w>=1)          ? exp(-(x[h,  w-1]-x[h,w])^2) + bias : bias
// G3[h,w] = (h<H-1 && w>=1) ? exp(-(x[h+1,w-1]-x[h,w])^2) + bias : bias
//
// 256-bit path (sm_103a): 8 floats per thread via LDG.256 / STG.256,
// halving L1tex/LTS request count vs the 128-bit version. Branchless
// (clamped row indices + selects).

#define H    512
#define WV8  64            // v8 (32B) chunks per row
#define N8   4194304u      // v8 chunks per gate tensor (4*32*512*512/8)

__device__ __forceinline__ void ldg256(const float* p, float* r) {
    unsigned u0,u1,u2,u3,u4,u5,u6,u7;
    asm volatile("ld.global.nc.v8.b32 {%0,%1,%2,%3,%4,%5,%6,%7}, [%8];"
                 : "=r"(u0),"=r"(u1),"=r"(u2),"=r"(u3),
                   "=r"(u4),"=r"(u5),"=r"(u6),"=r"(u7)
                 : "l"(p));
    r[0]=__uint_as_float(u0); r[1]=__uint_as_float(u1);
    r[2]=__uint_as_float(u2); r[3]=__uint_as_float(u3);
    r[4]=__uint_as_float(u4); r[5]=__uint_as_float(u5);
    r[6]=__uint_as_float(u6); r[7]=__uint_as_float(u7);
}

__device__ __forceinline__ void stg256(float* p, const float* r) {
    asm volatile("st.global.v8.b32 [%0], {%1,%2,%3,%4,%5,%6,%7,%8};"
                 :: "l"(p),
                    "r"(__float_as_uint(r[0])), "r"(__float_as_uint(r[1])),
                    "r"(__float_as_uint(r[2])), "r"(__float_as_uint(r[3])),
                    "r"(__float_as_uint(r[4])), "r"(__float_as_uint(r[5])),
                    "r"(__float_as_uint(r[6])), "r"(__float_as_uint(r[7]))
                 : "memory");
}

__global__ __launch_bounds__(256) void embeded_gate_kernel(
    const float* __restrict__ x,
    const float* __restrict__ bias,
    float* __restrict__ out)
{
    const unsigned j = blockIdx.x * 256u + threadIdx.x;   // v8 linear index
    const unsigned v = j & (WV8 - 1);
    const unsigned h = (j >> 6) & (H - 1);
    const unsigned c = (j >> 15) & 31u;

    const float bi = __ldg(&bias[c]);

    const bool hup = (h > 0);
    const bool hdn = (h < H - 1);
    const bool vs  = (v > 0);

    // clamped neighbor-row v8 indices (always in-bounds)
    const unsigned iu = hup ? j - WV8 : j;
    const unsigned id = hdn ? j + WV8 : j;
    const unsigned dv = vs ? 1u : 0u;   // scalar left-neighbor offset

    // ---- 6 unconditional, independent loads (front-batched) ----
    float cur[8], up8[8], dn8[8];
    ldg256(x + (j  << 3), cur);
    ldg256(x + (iu << 3), up8);
    ldg256(x + (id << 3), dn8);
    const float lc = __ldg(&x[(j  << 3) - dv]);
    const float lu = __ldg(&x[(iu << 3) - dv]);
    const float ld = __ldg(&x[(id << 3) - dv]);

    // shifted (w-1) views
    float lf[8], up[8], dn[8];
    lf[0] = lc; up[0] = lu; dn[0] = ld;
#pragma unroll
    for (int k = 1; k < 8; ++k) {
        lf[k] = cur[k - 1];
        up[k] = up8[k - 1];
        dn[k] = dn8[k - 1];
    }

    float g1[8], g2[8], g3[8];
#pragma unroll
    for (int k = 0; k < 8; ++k) {
        const bool wok = vs || (k > 0);     // global w index > 0
        float e1 = up[k] - cur[k];
        float e2 = lf[k] - cur[k];
        float e3 = dn[k] - cur[k];
        float v1 = __expf(-e1 * e1) + bi;
        float v2 = __expf(-e2 * e2) + bi;
        float v3 = __expf(-e3 * e3) + bi;
        g1[k] = (hup && wok) ? v1 : bi;
        g2[k] = (wok)        ? v2 : bi;
        g3[k] = (hdn && wok) ? v3 : bi;
    }

    stg256(out + ((unsigned long long)j << 3),                 g1);
    stg256(out + (((unsigned long long)j + N8) << 3),          g2);
    stg256(out + (((unsigned long long)j + 2ull * N8) << 3),   g3);
}

extern "C" void kernel_launch(void* const* d_in, const int* in_sizes, int n_in,
                              void* d_out, int out_size) {
    const float* x    = (const float*)d_in[0];
    const float* bias = (const float*)d_in[1];
    float* out = (float*)d_out;

    const long long total_v8 = (long long)in_sizes[0] / 8;    // 4,194,304 threads
    const int threads = 256;
    const int blocks = (int)((total_v8 + threads - 1) / threads);

    embeded_gate_kernel<<<blocks, threads>>>(x, bias, out);
}